// round 17
// baseline (speedup 1.0000x reference)
#include <cuda_runtime.h>
#include <cuda_bf16.h>
#include <math.h>
#include <stdint.h>

#define BB   64
#define SS   512
#define DD   128
#define DH   64
#define RTOT (BB*SS)

static constexpr size_t SZ       = (size_t)RTOT * DD;
static constexpr size_t OFF_T    = 0;
static constexpr size_t OFF_QKV  = 3*SZ;
static constexpr size_t OFF_CTX  = 21*SZ;
static constexpr size_t OFF_OUT3 = 27*SZ;
static constexpr size_t OFF_VSUM = 30*SZ;
static constexpr size_t OFF_GX   = OFF_VSUM + 49152;
static constexpr size_t GX_PER   = (size_t)RTOT * 384;
static constexpr size_t OFF_WHHT = OFF_GX + 6*GX_PER;
static constexpr size_t OFF_HSUM = OFF_WHHT + 6*49152;
static constexpr size_t OFF_OM   = OFF_HSUM + 49152;
static constexpr size_t SCRATCH_TOTAL = OFF_OM + 24576;

__device__ float g_scratch[SCRATCH_TOTAL];

// bf16 hi/lo weight images in B-fragment order (per 16-K chunk: 1024 hi | 1024 lo words)
static constexpr size_t IMG_QKVD = 0;
static constexpr size_t IMG_WIH  = IMG_QKVD + (size_t)24*16384;
static constexpr size_t IMG_PROJ = IMG_WIH  + (size_t)18*16384;
static constexpr size_t IMG_TOTAL = IMG_PROJ + (size_t)27*2048;

__device__ uint32_t g_img[IMG_TOTAL];

// ---------------- packed fp32x2 FMA (GRU) ----------------
__device__ __forceinline__ void ffma2(float2& d, float2 a, float2 b) {
    asm("fma.rn.f32x2 %0, %1, %2, %0;"
        : "+l"(reinterpret_cast<unsigned long long&>(d))
        : "l"(reinterpret_cast<unsigned long long&>(a)),
          "l"(reinterpret_cast<unsigned long long&>(b)));
}

// ---------------- bf16 split helpers ----------------
__device__ __forceinline__ uint32_t pack_hi(float f0, float f1) {
    __nv_bfloat16 h0 = __float2bfloat16(f0), h1 = __float2bfloat16(f1);
    return (uint32_t)__bfloat16_as_ushort(h0) | ((uint32_t)__bfloat16_as_ushort(h1) << 16);
}
__device__ __forceinline__ uint32_t pack_lo(float f0, float f1) {
    __nv_bfloat16 h0 = __float2bfloat16(f0), h1 = __float2bfloat16(f1);
    __nv_bfloat16 b0 = __float2bfloat16(f0 - __bfloat162float(h0));
    __nv_bfloat16 b1 = __float2bfloat16(f1 - __bfloat162float(h1));
    return (uint32_t)__bfloat16_as_ushort(b0) | ((uint32_t)__bfloat16_as_ushort(b1) << 16);
}

// ---------------- mma.sync m16n8k16 row.col f32.bf16 ----------------
__device__ __forceinline__ void hmma(float (&d)[4], const uint32_t (&a)[4], const uint32_t (&b)[2]) {
    asm volatile("mma.sync.aligned.m16n8k16.row.col.f32.bf16.bf16.f32 "
        "{%0,%1,%2,%3}, {%4,%5,%6,%7}, {%8,%9}, {%0,%1,%2,%3};"
        : "+f"(d[0]), "+f"(d[1]), "+f"(d[2]), "+f"(d[3])
        : "r"(a[0]), "r"(a[1]), "r"(a[2]), "r"(a[3]), "r"(b[0]), "r"(b[1]));
}

// ---------------- prepack kernels ----------------
__global__ __launch_bounds__(128)
void prepack_sq(const float* __restrict__ Wq, const float* __restrict__ Wk,
                const float* __restrict__ Wv, const float* __restrict__ Wd)
{
    int m = blockIdx.x, n = threadIdx.x;
    const float* W = (m < 6) ? Wq + (size_t)m*16384 : (m < 12) ? Wk + (size_t)(m-6)*16384
                   : (m < 18) ? Wv + (size_t)(m-12)*16384 : Wd + (size_t)(m-18)*16384;
    uint32_t* img = g_img + IMG_QKVD + (size_t)m*16384;
    for (int c = 0; c < 8; c++)
        for (int w = 0; w < 8; w++) {
            int k = c*16 + 2*w;
            float f0 = W[(size_t)k*128 + n], f1 = W[(size_t)(k+1)*128 + n];
            img[c*2048 + n*8 + w]        = pack_hi(f0, f1);
            img[c*2048 + 1024 + n*8 + w] = pack_lo(f0, f1);
        }
}

__global__ __launch_bounds__(128)
void prepack_wih(const float* __restrict__ gWih)
{
    int m = blockIdx.x, n = threadIdx.x;
    const float* src = gWih + (size_t)(m/3)*384*128 + (size_t)(m%3)*128*128 + (size_t)n*128;
    uint32_t* img = g_img + IMG_WIH + (size_t)m*16384;
    for (int c = 0; c < 8; c++)
        for (int w = 0; w < 8; w++) {
            int k = c*16 + 2*w;
            img[c*2048 + n*8 + w]        = pack_hi(src[k], src[k+1]);
            img[c*2048 + 1024 + n*8 + w] = pack_lo(src[k], src[k+1]);
        }
}

__global__ __launch_bounds__(128)
void prepack_proj(const float* __restrict__ fc1W, const float* __restrict__ fc2W,
                  const float* __restrict__ fc3W)
{
    int blk = blockIdx.x, n = threadIdx.x;
    int z, c;
    if (blk < 19)      { z = 0; c = blk; }
    else if (blk < 22) { z = 1; c = blk - 19; }
    else               { z = 2; c = blk - 22; }
    const int Kt[3] = {300, 35, 74};
    const size_t base[3] = {0, (size_t)19*2048, (size_t)22*2048};
    int K = Kt[z];
    const float* W = (z == 0) ? fc1W : (z == 1) ? fc2W : fc3W;
    uint32_t* img = g_img + IMG_PROJ + base[z] + (size_t)c*2048;
    for (int w = 0; w < 8; w++) {
        int k = c*16 + 2*w;
        float f0 = (k     < K) ? W[(size_t)k*128 + n]     : 0.f;
        float f1 = (k + 1 < K) ? W[(size_t)(k+1)*128 + n] : 0.f;
        img[n*8 + w]        = pack_hi(f0, f1);
        img[1024 + n*8 + w] = pack_lo(f0, f1);
    }
}

// ---------------- MMA GEMM core (validated R16) ----------------
__device__ __forceinline__ void mm_core(const float* __restrict__ A, int lda, int K,
                                        int nc, int vec, const uint32_t* __restrict__ img,
                                        uint32_t* sAh, uint32_t* sAl,
                                        uint32_t* sBh, uint32_t* sBl,
                                        float (&acc)[4][4][4])
{
    int tid = threadIdx.x;
    int lane = tid & 31, wid = tid >> 5;
    int g = lane >> 2, tig = lane & 3;
    int wr = wid & 1, wc = wid >> 1;
    int srow = tid >> 1, shalf = tid & 1;
    const uint4* img4 = (const uint4*)img;

    float f[8];
    uint4 pbh, pbl;
    {
        int k0 = shalf*8;
        if (vec && k0 + 8 <= K) {
            float4 x = *(const float4*)&A[(size_t)srow*lda + k0];
            float4 y = *(const float4*)&A[(size_t)srow*lda + k0 + 4];
            f[0]=x.x; f[1]=x.y; f[2]=x.z; f[3]=x.w; f[4]=y.x; f[5]=y.y; f[6]=y.z; f[7]=y.w;
        } else {
#pragma unroll
            for (int i = 0; i < 8; i++) { int k = k0+i; f[i] = (k < K) ? A[(size_t)srow*lda + k] : 0.f; }
        }
        pbh = img4[tid];
        pbl = img4[256 + tid];
    }

    for (int c = 0; c < nc; c++) {
        *(uint4*)&sAh[srow*8 + shalf*4] = make_uint4(pack_hi(f[0],f[1]), pack_hi(f[2],f[3]),
                                                     pack_hi(f[4],f[5]), pack_hi(f[6],f[7]));
        *(uint4*)&sAl[srow*8 + shalf*4] = make_uint4(pack_lo(f[0],f[1]), pack_lo(f[2],f[3]),
                                                     pack_lo(f[4],f[5]), pack_lo(f[6],f[7]));
        ((uint4*)sBh)[tid] = pbh;
        ((uint4*)sBl)[tid] = pbl;
        __syncthreads();

        if (c + 1 < nc) {
            int k0 = (c+1)*16 + shalf*8;
            if (vec && k0 + 8 <= K) {
                float4 x = *(const float4*)&A[(size_t)srow*lda + k0];
                float4 y = *(const float4*)&A[(size_t)srow*lda + k0 + 4];
                f[0]=x.x; f[1]=x.y; f[2]=x.z; f[3]=x.w; f[4]=y.x; f[5]=y.y; f[6]=y.z; f[7]=y.w;
            } else {
#pragma unroll
                for (int i = 0; i < 8; i++) { int k = k0+i; f[i] = (k < K) ? A[(size_t)srow*lda + k] : 0.f; }
            }
            pbh = img4[(size_t)(c+1)*512 + tid];
            pbl = img4[(size_t)(c+1)*512 + 256 + tid];
        }

        uint32_t ah[4][4], al[4][4];
#pragma unroll
        for (int i = 0; i < 4; i++) {
            int r0 = (wr*64 + i*16 + g)*8;
            ah[i][0] = sAh[r0+tig];   ah[i][1] = sAh[r0+64+tig];
            ah[i][2] = sAh[r0+4+tig]; ah[i][3] = sAh[r0+68+tig];
            al[i][0] = sAl[r0+tig];   al[i][1] = sAl[r0+64+tig];
            al[i][2] = sAl[r0+4+tig]; al[i][3] = sAl[r0+68+tig];
        }
#pragma unroll
        for (int j = 0; j < 4; j++) {
            int nb = (wc*32 + j*8 + g)*8;
            uint32_t bh[2] = {sBh[nb+tig], sBh[nb+4+tig]};
            uint32_t bl[2] = {sBl[nb+tig], sBl[nb+4+tig]};
#pragma unroll
            for (int i = 0; i < 4; i++) {
                hmma(acc[i][j], ah[i], bh);
                hmma(acc[i][j], al[i], bh);
                hmma(acc[i][j], ah[i], bl);
            }
        }
        __syncthreads();
    }
}

__device__ __forceinline__ void mm_epi_plain(float (&acc)[4][4][4], const float* sbias,
                                             float* __restrict__ C, int ldc,
                                             int rowbase, int nbase)
{
    int tid = threadIdx.x;
    int lane = tid & 31, wid = tid >> 5;
    int g = lane >> 2, tig = lane & 3;
    int wr = wid & 1, wc = wid >> 1;
#pragma unroll
    for (int i = 0; i < 4; i++) {
        int r0 = rowbase + wr*64 + i*16 + g;
#pragma unroll
        for (int j = 0; j < 4; j++) {
            int lc = wc*32 + j*8 + tig*2;
            float b0 = sbias[lc], b1 = sbias[lc+1];
            *(float2*)(C + (size_t)r0*ldc + nbase + lc)     = make_float2(acc[i][j][0]+b0, acc[i][j][1]+b1);
            *(float2*)(C + (size_t)(r0+8)*ldc + nbase + lc) = make_float2(acc[i][j][2]+b0, acc[i][j][3]+b1);
        }
    }
}

#define MM_ACC_INIT float acc[4][4][4]; \
    _Pragma("unroll") for (int i=0;i<4;i++) _Pragma("unroll") for (int j=0;j<4;j++) \
    _Pragma("unroll") for (int q=0;q<4;q++) acc[i][j][q]=0.f;

__global__ __launch_bounds__(256)
void mm_proj(const float* __restrict__ a0, const float* __restrict__ a1,
             const float* __restrict__ a2, const float* __restrict__ b0,
             const float* __restrict__ b1, const float* __restrict__ b2)
{
    __shared__ uint32_t sAh[1024], sAl[1024], sBh[1024], sBl[1024];
    __shared__ float sbias[128];
    const int Kt[3] = {300, 35, 74};
    const int nct[3] = {19, 3, 5};
    const size_t base[3] = {0, (size_t)19*2048, (size_t)22*2048};
    int tid = threadIdx.x, z = blockIdx.z;
    int rowbase = blockIdx.x * 128;
    int K = Kt[z];
    const float* A = ((z == 0) ? a0 : (z == 1) ? a1 : a2) + (size_t)rowbase*K;
    if (tid < 128) sbias[tid] = ((z == 0) ? b0 : (z == 1) ? b1 : b2)[tid];
    MM_ACC_INIT
    mm_core(A, K, K, nct[z], (z == 0) ? 1 : 0, g_img + IMG_PROJ + base[z], sAh, sAl, sBh, sBl, acc);
    mm_epi_plain(acc, sbias, g_scratch + OFF_T + (size_t)z*SZ, 128, rowbase, 0);
}

__global__ __launch_bounds__(256)
void mm_qkv(const float* __restrict__ bq, const float* __restrict__ bk,
            const float* __restrict__ bv)
{
    __shared__ uint32_t sAh[1024], sAl[1024], sBh[1024], sBl[1024];
    __shared__ float sbias[128];
    const int qsel[6] = {0,2,0,1,1,2};
    const int ksel[6] = {2,0,1,0,2,1};
    int tid = threadIdx.x, z = blockIdx.z;
    int unit = z / 3, which = z % 3;
    int src = (which == 0) ? qsel[unit] : ksel[unit];
    int rowbase = blockIdx.x * 128;
    const float* A = g_scratch + OFF_T + (size_t)src*SZ + (size_t)rowbase*128;
    if (tid < 128) sbias[tid] = (((which == 0) ? bq : (which == 1) ? bk : bv) + unit*128)[tid];
    MM_ACC_INIT
    mm_core(A, 128, 128, 8, 1, g_img + IMG_QKVD + (size_t)(which*6 + unit)*16384,
            sAh, sAl, sBh, sBl, acc);
    mm_epi_plain(acc, sbias, g_scratch + OFF_QKV + (size_t)z*SZ, 128, rowbase, 0);
}

__global__ __launch_bounds__(256)
void mm_gx(const float* __restrict__ gbih)
{
    __shared__ uint32_t sAh[1024], sAl[1024], sBh[1024], sBl[1024];
    __shared__ float sbias[128];
    int tid = threadIdx.x;
    int dir = blockIdx.z, ntile = blockIdx.y;
    int rowbase = blockIdx.x * 128;
    int nbase = ntile*128;
    const float* A = g_scratch + OFF_OUT3 + (size_t)(dir >> 1)*SZ + (size_t)rowbase*128;
    if (tid < 128) sbias[tid] = gbih[dir*384 + nbase + tid];
    MM_ACC_INIT
    mm_core(A, 128, 128, 8, 1, g_img + IMG_WIH + (size_t)(dir*3 + ntile)*16384,
            sAh, sAl, sBh, sBl, acc);
    mm_epi_plain(acc, sbias, g_scratch + OFF_GX + (size_t)dir*GX_PER, 384, rowbase, nbase);
}

__global__ __launch_bounds__(256)
void mm_ln(const float* __restrict__ bd, const float* __restrict__ lng,
           const float* __restrict__ lnb, int phase)
{
    __shared__ uint32_t sAh[1024], sAl[1024], sBh[1024], sBl[1024];
    __shared__ float sbias[128], slg[128], slb[128];
    __shared__ float ssum[512], ssum2[512];
    __shared__ float smean[128], srstd[128];
    const int accsel[6] = {2,0,1,0,2,1};
    int tid = threadIdx.x;
    int unit = phase*3 + blockIdx.z;
    int rowbase = blockIdx.x * 128;
    const float* A = g_scratch + OFF_CTX + (size_t)unit*SZ + (size_t)rowbase*128;
    float* C = g_scratch + OFF_OUT3 + (size_t)accsel[unit]*SZ;
    if (tid < 128) {
        sbias[tid] = bd[unit*128 + tid];
        slg[tid]   = lng[unit*128 + tid];
        slb[tid]   = lnb[unit*128 + tid];
    }
    MM_ACC_INIT
    mm_core(A, 128, 128, 8, 1, g_img + IMG_QKVD + (size_t)(18 + unit)*16384,
            sAh, sAl, sBh, sBl, acc);

    int lane = tid & 31, wid = tid >> 5;
    int g = lane >> 2, tig = lane & 3;
    int wr = wid & 1, wc = wid >> 1;
#pragma unroll
    for (int i = 0; i < 4; i++) {
        float s0 = 0.f, q0 = 0.f, s8 = 0.f, q8 = 0.f;
#pragma unroll
        for (int j = 0; j < 4; j++) {
            int lc = wc*32 + j*8 + tig*2;
            float b0 = sbias[lc], b1 = sbias[lc+1];
            acc[i][j][0] += b0; acc[i][j][1] += b1;
            acc[i][j][2] += b0; acc[i][j][3] += b1;
            s0 += acc[i][j][0] + acc[i][j][1];
            q0 += acc[i][j][0]*acc[i][j][0] + acc[i][j][1]*acc[i][j][1];
            s8 += acc[i][j][2] + acc[i][j][3];
            q8 += acc[i][j][2]*acc[i][j][2] + acc[i][j][3]*acc[i][j][3];
        }
#pragma unroll
        for (int off = 1; off <= 2; off <<= 1) {
            s0 += __shfl_xor_sync(0xffffffffu, s0, off);
            q0 += __shfl_xor_sync(0xffffffffu, q0, off);
            s8 += __shfl_xor_sync(0xffffffffu, s8, off);
            q8 += __shfl_xor_sync(0xffffffffu, q8, off);
        }
        if (tig == 0) {
            int r0 = wr*64 + i*16 + g;
            ssum[r0*4 + wc] = s0;      ssum2[r0*4 + wc] = q0;
            ssum[(r0+8)*4 + wc] = s8;  ssum2[(r0+8)*4 + wc] = q8;
        }
    }
    __syncthreads();
    if (tid < 128) {
        float s = ssum[tid*4] + ssum[tid*4+1] + ssum[tid*4+2] + ssum[tid*4+3];
        float q = ssum2[tid*4] + ssum2[tid*4+1] + ssum2[tid*4+2] + ssum2[tid*4+3];
        float mean = s * (1.0f/128.0f);
        float var  = q * (1.0f/128.0f) - mean*mean;
        smean[tid] = mean;
        srstd[tid] = rsqrtf(var + 1e-5f);
    }
    __syncthreads();
#pragma unroll
    for (int i = 0; i < 4; i++) {
        int rl = wr*64 + i*16 + g;
        float m0 = smean[rl],   rs0 = srstd[rl];
        float m8 = smean[rl+8], rs8 = srstd[rl+8];
#pragma unroll
        for (int j = 0; j < 4; j++) {
            int lc = wc*32 + j*8 + tig*2;
            float g0 = slg[lc], g1 = slg[lc+1], t0 = slb[lc], t1 = slb[lc+1];
            float o0 = 0.5f*((acc[i][j][0]-m0)*rs0*g0 + t0);
            float o1 = 0.5f*((acc[i][j][1]-m0)*rs0*g1 + t1);
            float o2 = 0.5f*((acc[i][j][2]-m8)*rs8*g0 + t0);
            float o3 = 0.5f*((acc[i][j][3]-m8)*rs8*g1 + t1);
            float* p0 = C + (size_t)(rowbase+rl)*128 + lc;
            float* p1 = C + (size_t)(rowbase+rl+8)*128 + lc;
            if (phase == 0) {
                *(float2*)p0 = make_float2(o0, o1);
                *(float2*)p1 = make_float2(o2, o3);
            } else {
                float2 v0 = *(float2*)p0, v1 = *(float2*)p1;
                *(float2*)p0 = make_float2(v0.x + o0, v0.y + o1);
                *(float2*)p1 = make_float2(v1.x + o2, v1.y + o3);
            }
        }
    }
}

// ---------------- V column sums ----------------
__global__ void vsum_kernel()
{
    int b = blockIdx.x, h = blockIdx.y, u = blockIdx.z, d = threadIdx.x;
    const float* V = g_scratch + OFF_QKV + (size_t)(u*3 + 2)*SZ + (size_t)b*SS*DD + h*DH + d;
    float s = 0.f;
#pragma unroll 8
    for (int k = 0; k < SS; k++) s += V[(size_t)k*DD];
    g_scratch[OFF_VSUM + (((size_t)u*64 + b)*2 + h)*64 + d] = s;
}

// ---------------- HMMA attention: ctx = Vsum - softmax(QK^T/8)@V ----------------
// grid (16 qtiles of 32 rows, 128 bh, 6 u), 256 threads, 91520 B smem.
#define ATT_SMEM 91520

__global__ __launch_bounds__(256, 2)
void attn_mma()
{
    extern __shared__ char smc[];
    uint32_t* qh  = (uint32_t*)smc;              // Q hi  [32][33]
    uint32_t* ql  = (uint32_t*)(smc + 4224);     // Q lo
    uint32_t* kvh = (uint32_t*)(smc + 8448);     // K hi [64][33] u32 / V hi [64][66] u16
    uint32_t* kvl = (uint32_t*)(smc + 16896);
    float*    sS  = (float*)(smc + 25344);       // [32][516] scores, then packed P
    float*    rowl = (float*)(smc + 91392);      // [32]

    int tid = threadIdx.x;
    int lane = tid & 31, wid = tid >> 5;
    int g = lane >> 2, tig = lane & 3;
    int wq = wid & 1, wn = wid >> 1;

    int u = blockIdx.z, bh = blockIdx.y;
    int b = bh >> 1, h = bh & 1;
    int q0 = blockIdx.x * 32;

    const float* Qb = g_scratch + OFF_QKV + (size_t)(u*3+0)*SZ + ((size_t)b*SS + q0)*DD + h*DH;
    const float* Kb = g_scratch + OFF_QKV + (size_t)(u*3+1)*SZ + (size_t)b*SS*DD + h*DH;
    const float* Vb = g_scratch + OFF_QKV + (size_t)(u*3+2)*SZ + (size_t)b*SS*DD + h*DH;

    // stage Q hi/lo
#pragma unroll
    for (int p = 0; p < 4; p++) {
        int idx = tid + p*256;
        int row = idx >> 5, w = idx & 31;
        float2 f = *(const float2*)&Qb[(size_t)row*DD + 2*w];
        qh[row*33 + w] = pack_hi(f.x, f.y);
        ql[row*33 + w] = pack_lo(f.x, f.y);
    }

    // ---- phase 1: S = Q K^T / 8 ----
    for (int kt = 0; kt < 8; kt++) {
        __syncthreads();
#pragma unroll
        for (int p = 0; p < 8; p++) {
            int idx = tid + p*256;
            int key = idx >> 5, w = idx & 31;
            float2 f = *(const float2*)&Kb[(size_t)(kt*64 + key)*DD + 2*w];
            kvh[key*33 + w] = pack_hi(f.x, f.y);
            kvl[key*33 + w] = pack_lo(f.x, f.y);
        }
        __syncthreads();

        float acc[2][4];
#pragma unroll
        for (int j = 0; j < 2; j++)
#pragma unroll
            for (int q = 0; q < 4; q++) acc[j][q] = 0.f;
#pragma unroll
        for (int c = 0; c < 4; c++) {
            uint32_t ah[4], al[4];
            int r0 = (wq*16 + g)*33 + c*8;
            ah[0] = qh[r0+tig]; ah[1] = qh[r0+8*33+tig];
            ah[2] = qh[r0+4+tig]; ah[3] = qh[r0+8*33+4+tig];
            al[0] = ql[r0+tig]; al[1] = ql[r0+8*33+tig];
            al[2] = ql[r0+4+tig]; al[3] = ql[r0+8*33+4+tig];
#pragma unroll
            for (int j = 0; j < 2; j++) {
                int nb = (wn*16 + j*8 + g)*33 + c*8;
                uint32_t bhf[2] = {kvh[nb+tig], kvh[nb+4+tig]};
                uint32_t blf[2] = {kvl[nb+tig], kvl[nb+4+tig]};
                hmma(acc[j], ah, bhf);
                hmma(acc[j], al, bhf);
                hmma(acc[j], ah, blf);
            }
        }
#pragma unroll
        for (int j = 0; j < 2; j++) {
            int col = kt*64 + wn*16 + j*8 + tig*2;
            *(float2*)&sS[(wq*16+g)*516 + col]   = make_float2(acc[j][0]*0.125f, acc[j][1]*0.125f);
            *(float2*)&sS[(wq*16+g+8)*516 + col] = make_float2(acc[j][2]*0.125f, acc[j][3]*0.125f);
        }
    }
    __syncthreads();

    // ---- phase 2: row softmax (unnormalized), pack P hi/lo in place ----
#pragma unroll
    for (int r = 0; r < 4; r++) {
        int row = wid*4 + r;
        float* srow = sS + row*516;
        const float4* s4 = (const float4*)srow;
        float v[16];
#pragma unroll
        for (int i = 0; i < 4; i++) {
            float4 x = s4[lane*4 + i];
            v[i*4+0] = x.x; v[i*4+1] = x.y; v[i*4+2] = x.z; v[i*4+3] = x.w;
        }
        float m = v[0];
#pragma unroll
        for (int i = 1; i < 16; i++) m = fmaxf(m, v[i]);
#pragma unroll
        for (int off = 16; off >= 1; off >>= 1)
            m = fmaxf(m, __shfl_xor_sync(0xffffffffu, m, off));
        float s = 0.f;
#pragma unroll
        for (int i = 0; i < 16; i++) { v[i] = __expf(v[i] - m); s += v[i]; }
#pragma unroll
        for (int off = 16; off >= 1; off >>= 1)
            s += __shfl_xor_sync(0xffffffffu, s, off);
        if (lane == 0) rowl[row] = s;
        uint32_t* prow = (uint32_t*)srow;   // lane writes only words it read
#pragma unroll
        for (int j = 0; j < 8; j++) {
            prow[lane*16 + j]     = pack_hi(v[2*j], v[2*j+1]);
            prow[lane*16 + 8 + j] = pack_lo(v[2*j], v[2*j+1]);
        }
    }

    // ---- phase 3: O = P V ----
    float oacc[2][4];
#pragma unroll
    for (int j = 0; j < 2; j++)
#pragma unroll
        for (int q = 0; q < 4; q++) oacc[j][q] = 0.f;

    for (int kt = 0; kt < 8; kt++) {
        __syncthreads();
#pragma unroll
        for (int p = 0; p < 8; p++) {
            int idx = tid + p*256;
            int key = idx >> 5, w = idx & 31;          // w = d-pair
            float2 f = *(const float2*)&Vb[(size_t)(kt*64 + key)*DD + 2*w];
            __nv_bfloat16 h0 = __float2bfloat16(f.x), h1 = __float2bfloat16(f.y);
            ((unsigned short*)kvh)[(2*w)*66 + key]   = __bfloat16_as_ushort(h0);
            ((unsigned short*)kvh)[(2*w+1)*66 + key] = __bfloat16_as_ushort(h1);
            ((unsigned short*)kvl)[(2*w)*66 + key]   =
                __bfloat16_as_ushort(__float2bfloat16(f.x - __bfloat162float(h0)));
            ((unsigned short*)kvl)[(2*w+1)*66 + key] =
                __bfloat16_as_ushort(__float2bfloat16(f.y - __bfloat162float(h1)));
        }
        __syncthreads();

        const uint32_t* pr0 = (const uint32_t*)(sS + (size_t)(wq*16+g)*516);
        const uint32_t* pr8 = (const uint32_t*)(sS + (size_t)(wq*16+g+8)*516);
#pragma unroll
        for (int c = 0; c < 4; c++) {
            int cg = kt*4 + c;
            int i0 = cg*16 + tig, i1 = cg*16 + 4 + tig;
            uint32_t ah[4] = {pr0[i0], pr8[i0], pr0[i1], pr8[i1]};
            uint32_t al[4] = {pr0[i0+8], pr8[i0+8], pr0[i1+8], pr8[i1+8]};
#pragma unroll
            for (int j = 0; j < 2; j++) {
                int nb = (wn*16 + j*8 + g)*33 + c*8;
                uint32_t bhf[2] = {kvh[nb+tig], kvh[nb+4+tig]};
                uint32_t blf[2] = {kvl[nb+tig], kvl[nb+4+tig]};
                hmma(oacc[j], ah, bhf);
                hmma(oacc[j], al, bhf);
                hmma(oacc[j], ah, blf);
            }
        }
    }
    __syncthreads();

    // ---- epilogue: ctx = Vsum - O / l ----
    float inv0 = 1.f / rowl[wq*16 + g];
    float inv8 = 1.f / rowl[wq*16 + g + 8];
    const float* vs = g_scratch + OFF_VSUM + (((size_t)u*64 + b)*2 + h)*64;
    float* Cb = g_scratch + OFF_CTX + (size_t)u*SZ;
#pragma unroll
    for (int j = 0; j < 2; j++) {
        int col = wn*16 + j*8 + tig*2;
        float2 v2 = *(const float2*)&vs[col];
        size_t o0 = ((size_t)b*SS + q0 + wq*16 + g)*DD + h*DH + col;
        *(float2*)&Cb[o0]        = make_float2(v2.x - oacc[j][0]*inv0, v2.y - oacc[j][1]*inv0);
        *(float2*)&Cb[o0 + 8*DD] = make_float2(v2.x - oacc[j][2]*inv8, v2.y - oacc[j][3]*inv8);
    }
}

// ---------------- Whh transpose (parallelized) ----------------
__global__ void transpose_whh(const float* __restrict__ gWhh)
{
    int m = blockIdx.x, slice = blockIdx.y;
    const float* src = gWhh + (size_t)m*384*128;
    float* dst = g_scratch + OFF_WHHT + (size_t)m*49152;
    int base = slice * 6144;
    for (int i = threadIdx.x; i < 6144; i += blockDim.x) {
        int idx = base + i;
        int k = idx / 384, n = idx % 384;
        dst[idx] = src[(size_t)n*128 + k];
    }
}

// ---------------- GRU recurrence ----------------
__global__ __launch_bounds__(384)
void gru_kernel(const float* __restrict__ gbhh)
{
    int dir6 = blockIdx.x >> 6;
    int b    = blockIdx.x & 63;
    int j    = threadIdx.x;

    const float* wp = g_scratch + OFF_WHHT + (size_t)dir6*49152 + j;
    float2 w2[64];
#pragma unroll
    for (int k = 0; k < 64; k++)
        w2[k] = make_float2(wp[(size_t)(2*k)*384], wp[(size_t)(2*k + 1)*384]);
    float bh = gbhh[dir6*384 + j];

    __shared__ float h[128];
    __shared__ float gh[384];
    __shared__ float gxs[384];
    __shared__ float hs[128];
    if (j < 128) { h[j] = 0.f; hs[j] = 0.f; }

    const float* gxb = g_scratch + OFF_GX + (size_t)dir6*GX_PER + (size_t)b*SS*384;
    int rev = dir6 & 1;
    const float2* h2 = (const float2*)h;

    for (int step = 0; step < SS; step++) {
        int t = rev ? (SS - 1 - step) : step;
        float gxv = gxb[(size_t)t*384 + j];
        __syncthreads();
        gxs[j] = gxv;
        float2 acc = make_float2(0.f, 0.f);
#pragma unroll
        for (int k = 0; k < 64; k++) ffma2(acc, w2[k], h2[k]);
        gh[j] = acc.x + acc.y + bh;
        __syncthreads();
        if (j < 128) {
            float r  = 1.f / (1.f + __expf(-(gxs[j]       + gh[j])));
            float z  = 1.f / (1.f + __expf(-(gxs[128 + j] + gh[128 + j])));
            float n  = tanhf(gxs[256 + j] + r * gh[256 + j]);
            float hn = (1.f - z)*n + z*h[j];
            h[j]  = hn;
            hs[j] += hn;
        }
    }
    __syncthreads();
    if (j < 128) g_scratch[OFF_HSUM + ((size_t)dir6*64 + b)*128 + j] = hs[j];
}

// ---------------- combine + head ----------------
__global__ void combine_kernel()
{
    int b = blockIdx.x, j = threadIdx.x;
    int seg = j >> 7, i = j & 127;
    float v = g_scratch[OFF_HSUM + ((size_t)seg*64 + b)*128 + i]
            + g_scratch[OFF_HSUM + ((size_t)(seg + 3)*64 + b)*128 + i];
    g_scratch[OFF_OM + (size_t)b*384 + j] = v * (0.5f / 512.0f);
}

__global__ __launch_bounds__(256)
void head_kernel(const float* __restrict__ fW1, const float* __restrict__ fb1,
                 const float* __restrict__ bng, const float* __restrict__ bnb,
                 const float* __restrict__ fW2, const float* __restrict__ fb2,
                 float* __restrict__ out)
{
    __shared__ float oms[384];
    __shared__ float hsh[256];
    int b = blockIdx.x, tid = threadIdx.x;
    for (int k = tid; k < 384; k += 256) oms[k] = g_scratch[OFF_OM + (size_t)b*384 + k];
    __syncthreads();
    float acc = fb1[tid];
    for (int k = 0; k < 384; k++) acc += oms[k] * fW1[(size_t)k*256 + tid];
    float hv = acc * rsqrtf(1.0f + 1e-5f) * bng[tid] + bnb[tid];
    hv = fminf(fmaxf(hv, 0.f), 6.f);
    hsh[tid] = hv;
    __syncthreads();
    if (tid < 8) {
        float a2 = fb2[tid];
        for (int k = 0; k < 256; k++) a2 += hsh[k] * fW2[k*8 + tid];
        out[b*8 + tid] = a2;
    }
}

// ---------------- host launcher ----------------
extern "C" void kernel_launch(void* const* d_in, const int* in_sizes, int n_in,
                              void* d_out, int out_size)
{
    (void)in_sizes; (void)n_in; (void)out_size;
    const float* text   = (const float*)d_in[0];
    const float* visual = (const float*)d_in[1];
    const float* audio  = (const float*)d_in[2];
    const float* fc1W = (const float*)d_in[3];
    const float* fc1b = (const float*)d_in[4];
    const float* fc2W = (const float*)d_in[5];
    const float* fc2b = (const float*)d_in[6];
    const float* fc3W = (const float*)d_in[7];
    const float* fc3b = (const float*)d_in[8];
    const float* Wq = (const float*)d_in[9];
    const float* bq = (const float*)d_in[10];
    const float* Wk = (const float*)d_in[11];
    const float* bk = (const float*)d_in[12];
    const float* Wv = (const float*)d_in[13];
    const float* bv = (const float*)d_in[14];
    const float* Wd = (const float*)d_in[15];
    const float* bd = (const float*)d_in[16];
    const float* lng = (const float*)d_in[17];
    const float* lnb = (const float*)d_in[18];
    const float* gWih = (const float*)d_in[19];
    const float* gWhh = (const float*)d_in[20];
    const float* gbih = (const float*)d_in[21];
    const float* gbhh = (const float*)d_in[22];
    const float* fW1 = (const float*)d_in[23];
    const float* fb1 = (const float*)d_in[24];
    const float* bng = (const float*)d_in[25];
    const float* bnb = (const float*)d_in[26];
    const float* fW2 = (const float*)d_in[27];
    const float* fb2 = (const float*)d_in[28];
    float* out = (float*)d_out;

    cudaFuncSetAttribute(attn_mma, cudaFuncAttributeMaxDynamicSharedMemorySize, ATT_SMEM);

    prepack_sq<<<24, 128>>>(Wq, Wk, Wv, Wd);
    prepack_wih<<<18, 128>>>(gWih);
    prepack_proj<<<27, 128>>>(fc1W, fc2W, fc3W);
    transpose_whh<<<dim3(6, 8), 256>>>(gWhh);

    mm_proj<<<dim3(RTOT/128, 1, 3), 256>>>(text, visual, audio, fc1b, fc2b, fc3b);
    mm_qkv<<<dim3(RTOT/128, 1, 18), 256>>>(bq, bk, bv);

    vsum_kernel<<<dim3(64, 2, 6), 64>>>();
    attn_mma<<<dim3(16, 128, 6), 256, ATT_SMEM>>>();

    mm_ln<<<dim3(RTOT/128, 1, 3), 256>>>(bd, lng, lnb, 0);
    mm_ln<<<dim3(RTOT/128, 1, 3), 256>>>(bd, lng, lnb, 1);

    mm_gx<<<dim3(RTOT/128, 3, 6), 256>>>(gbih);

    gru_kernel<<<384, 384>>>(gbhh);
    combine_kernel<<<64, 384>>>();
    head_kernel<<<64, 256>>>(fW1, fb1, bng, bnb, fW2, fb2, out);
}